// round 8
// baseline (speedup 1.0000x reference)
#include <cuda_runtime.h>
#include <cuda_fp16.h>

#define BB 2
#define LL 16
#define CC 16
#define HH 64
#define WW 64
#define HW (HH*WW)

#define PW 68                 // padded width in 32B pixel-chunks; 68*32 = 2176 = 17*128
#define PH 66                 // padded height (rows -1..64)
#define PCH (PW*PH)
#define IMG_BYTES (PCH*32)    // 143616

// Zero-padded channel-last fp16 image cache. Chunk (y,x) (32B = 16 halves) at
// chunk index (y+1)*PW + (x+1), for x,y in [-1,64].
__device__ uint4 g_pad[BB*LL*PCH*2];

// ---------------------------------------------------------------------------
// Kernel 1: images (B,L,C,H,W) fp32 -> padded channel-last fp16 (zero border)
// ---------------------------------------------------------------------------
__global__ __launch_bounds__(256) void pad_kernel(const float* __restrict__ images) {
    int i = blockIdx.x * 256 + threadIdx.x;      // [0, BB*LL*PCH)
    int bl = i / PCH;
    int s  = i - bl * PCH;
    int y  = s / PW;
    int x  = s - y * PW;
    uint4 v0 = make_uint4(0u,0u,0u,0u), v1 = v0;
    if (x >= 1 && x <= WW && y >= 1 && y <= HH) {
        int px = (y - 1) * WW + (x - 1);
        const float* sp = images + (size_t)bl * CC * HW + px;
        unsigned u[8];
#pragma unroll
        for (int c = 0; c < 8; c++) {
            __half2 hh = __floats2half2_rn(sp[(2*c) * HW], sp[(2*c+1) * HW]);
            u[c] = *(unsigned*)&hh;
        }
        v0 = make_uint4(u[0], u[1], u[2], u[3]);
        v1 = make_uint4(u[4], u[5], u[6], u[7]);
    }
    uint4* d = g_pad + (size_t)i * 2;
    d[0] = v0;
    d[1] = v1;
}

// ---------------------------------------------------------------------------
// Kernel 2: main. Lane = (pixel, k-slot): lane = plq*4 + kq, warp covers
// 8 pixels x 4 k's. Each lane does coordinate math ONCE per (pixel,k) task,
// gathers all 4 corners (4x16B top span + 4x16B bottom span, tl/tr contiguous),
// fp16 4-corner combine, fp32 per-slot accumulators; shfl merges k-slots.
// ---------------------------------------------------------------------------
__global__ __launch_bounds__(256) void main_kernel(const float* __restrict__ flows,
                                                   float* __restrict__ out) {
    __shared__ float2 scum[LL * 64];

    int bt  = blockIdx.x >> 6;        // 64 blocks per (b,t), 64 pixels each
    int blk = blockIdx.x & 63;
    int b   = bt >> 4;
    int t   = 15 - (bt & 15);         // heavy blocks first
    int p_base = blk * 64;
    int tid = threadIdx.x;

    // Fused cumsum: threads 0..127 = 64 pixels x 2 components.
    if (tid < 128) {
        int comp = tid >> 6;
        int pl   = tid & 63;
        const float* fb = flows + ((size_t)b * LL * 2 + comp) * HW + p_base + pl;
        float c = 0.0f;
#pragma unroll
        for (int l = 0; l < LL; l++) {
            c += fb[l * 2 * HW];
            ((float*)&scum[l * 64 + pl])[comp] = c;
        }
    }
    __syncthreads();

    int warp = tid >> 5;
    int lane = tid & 31;
    int plq  = lane >> 2;             // pixel within warp (0-7)
    int kq   = lane & 3;              // k-slot (0-3)
    int pl   = warp * 8 + plq;        // pixel within block (0-63)
    int p    = p_base + pl;
    int h    = p >> 6;
    int w    = p & 63;

    float2 ct = scum[t * 64 + pl];
    float cwx = (w + 0.5f) + 32.0f * ct.x;
    float cwy = (h + 0.5f) + 32.0f * ct.y;

    float acc[16];
#pragma unroll
    for (int e = 0; e < 16; e++) acc[e] = 0.0f;

    const char* ibase = (const char*)g_pad
                      + (size_t)(b * LL) * IMG_BYTES
                      + (size_t)(PW + 1) * 32;   // (+1,+1) pad origin

    for (int k0 = 0; k0 <= t; k0 += 4) {
        int k = k0 + kq;
        bool active = (k <= t);
        int ke = active ? k : t;

        float2 ck = scum[ke * 64 + pl];
        float uxp = fmaf(-32.0f, ck.x, cwx);
        float uyp = fmaf(-32.0f, ck.y, cwy);
        // mod into [0,64): rxm == true rx + 0.5
        float rxm = fmaf(-floorf(uxp * 0.015625f), 64.0f, uxp);
        float rym = fmaf(-floorf(uyp * 0.015625f), 64.0f, uyp);
        float rx0 = rxm - 0.5f;
        float ry0 = rym - 0.5f;
        float fx0 = floorf(rx0);
        float fy0 = floorf(ry0);
        int x0 = (int)fx0;            // [-1, 63]
        int y0 = (int)fy0;
        float sx = rx0 - fx0;
        float sy = ry0 - fy0;
        float axw = 1.0f - sx;
        float ayw = 1.0f - sy;
        if (!active) { sx = 0.0f; axw = 0.0f; }   // zero all 4 weights

        __half2 wtl = __float2half2_rn(axw * ayw);
        __half2 wtr = __float2half2_rn(sx  * ayw);
        __half2 wbl = __float2half2_rn(axw * sy);
        __half2 wbr = __float2half2_rn(sx  * sy);

        const char* a = ibase + (size_t)ke * IMG_BYTES + (y0 * PW + x0) * 32;
        uint4 tl0 = *(const uint4*)(a);
        uint4 tl1 = *(const uint4*)(a + 16);
        uint4 tr0 = *(const uint4*)(a + 32);
        uint4 tr1 = *(const uint4*)(a + 48);
        const char* ab = a + PW * 32;
        uint4 bl0 = *(const uint4*)(ab);
        uint4 bl1 = *(const uint4*)(ab + 16);
        uint4 br0 = *(const uint4*)(ab + 32);
        uint4 br1 = *(const uint4*)(ab + 48);

        const __half2* ptl0 = (const __half2*)&tl0;
        const __half2* ptr0 = (const __half2*)&tr0;
        const __half2* pbl0 = (const __half2*)&bl0;
        const __half2* pbr0 = (const __half2*)&br0;
#pragma unroll
        for (int j = 0; j < 4; j++) {
            __half2 hv = __hmul2(ptl0[j], wtl);
            hv = __hfma2(ptr0[j], wtr, hv);
            hv = __hfma2(pbl0[j], wbl, hv);
            hv = __hfma2(pbr0[j], wbr, hv);
            float2 f = __half22float2(hv);
            acc[2*j]     += f.x;
            acc[2*j + 1] += f.y;
        }
        const __half2* ptl1 = (const __half2*)&tl1;
        const __half2* ptr1 = (const __half2*)&tr1;
        const __half2* pbl1 = (const __half2*)&bl1;
        const __half2* pbr1 = (const __half2*)&br1;
#pragma unroll
        for (int j = 0; j < 4; j++) {
            __half2 hv = __hmul2(ptl1[j], wtl);
            hv = __hfma2(ptr1[j], wtr, hv);
            hv = __hfma2(pbl1[j], wbl, hv);
            hv = __hfma2(pbr1[j], wbr, hv);
            float2 f = __half22float2(hv);
            acc[8 + 2*j]     += f.x;
            acc[8 + 2*j + 1] += f.y;
        }
    }

    // Merge the 4 k-slots (lanes differing in bits 0-1).
#pragma unroll
    for (int e = 0; e < 16; e++) {
        acc[e] += __shfl_xor_sync(0xffffffffu, acc[e], 1);
        acc[e] += __shfl_xor_sync(0xffffffffu, acc[e], 2);
    }

    if (kq == 0) {
        // out layout (B,L,C,H,W); this lane owns all 16 channels of pixel p
        float* ob = out + (size_t)((b * LL + t) * CC) * HW + p;
#pragma unroll
        for (int c = 0; c < 16; c++) ob[c * HW] = acc[c];
    }
}

// ---------------------------------------------------------------------------
extern "C" void kernel_launch(void* const* d_in, const int* in_sizes, int n_in,
                              void* d_out, int out_size) {
    const float* flows  = (const float*)d_in[0];
    const float* images = (const float*)d_in[1];
    if (n_in >= 2 && in_sizes[0] > in_sizes[1]) {   // defensive: flows is smaller
        const float* tmp = flows; flows = images; images = tmp;
    }
    float* out = (float*)d_out;

    pad_kernel<<<(BB * LL * PCH + 255) / 256, 256>>>(images);
    main_kernel<<<BB * LL * 64, 256>>>(flows, out);
}

// round 9
// speedup vs baseline: 1.8970x; 1.8970x over previous
#include <cuda_runtime.h>
#include <cuda_fp16.h>

#define BB 2
#define LL 16
#define CC 16
#define HH 64
#define WW 64
#define HW (HH*WW)

#define PW 68                 // padded width in 32B pixel-chunks; 68*32 = 2176 = 17*128
#define PH 66                 // padded height (rows -1..64)
#define PCH (PW*PH)
#define IMG_BYTES (PCH*32)    // 143616

// Zero-padded channel-last fp16 image cache. Chunk (y,x) (32B = 16 halves) at
// chunk index (y+1)*PW + (x+1), for x,y in [-1,64].
__device__ uint4 g_pad[BB*LL*PCH*2];

// ---------------------------------------------------------------------------
// Kernel 1: images (B,L,C,H,W) fp32 -> padded channel-last fp16 (zero border)
// ---------------------------------------------------------------------------
__global__ __launch_bounds__(256) void pad_kernel(const float* __restrict__ images) {
    int i = blockIdx.x * 256 + threadIdx.x;      // [0, BB*LL*PCH)
    int bl = i / PCH;
    int s  = i - bl * PCH;
    int y  = s / PW;
    int x  = s - y * PW;
    uint4 v0 = make_uint4(0u,0u,0u,0u), v1 = v0;
    if (x >= 1 && x <= WW && y >= 1 && y <= HH) {
        int px = (y - 1) * WW + (x - 1);
        const float* sp = images + (size_t)bl * CC * HW + px;
        unsigned u[8];
#pragma unroll
        for (int c = 0; c < 8; c++) {
            __half2 hh = __floats2half2_rn(sp[(2*c) * HW], sp[(2*c+1) * HW]);
            u[c] = *(unsigned*)&hh;
        }
        v0 = make_uint4(u[0], u[1], u[2], u[3]);
        v1 = make_uint4(u[4], u[5], u[6], u[7]);
    }
    uint4* d = g_pad + (size_t)i * 2;
    d[0] = v0;
    d[1] = v1;
}

// ---------------------------------------------------------------------------
// Kernel 2: main. 4 lanes per pixel (q = (xq<<1)|cq): wavefront-optimal
// mapping — the 4 lanes of a pixel cover a contiguous 64B span per corner row.
// Each block computes TWO paired timesteps (15-r, r) => exactly 17 k-iters
// per block, uniform load, fully-resident single wave.
// fp16 accumulators: 2 HFMA2 per 16B sub-chunk per k, no converts in loop.
// ---------------------------------------------------------------------------
__global__ __launch_bounds__(256) void main_kernel(const float* __restrict__ flows,
                                                   float* __restrict__ out) {
    __shared__ float2 scum[LL * 64];

    int idx = blockIdx.x;             // [0, 1024): b(2) x r(8) x blk(64)
    int blk = idx & 63;
    int r   = (idx >> 6) & 7;
    int b   = idx >> 9;
    int p_base = blk * 64;
    int tid = threadIdx.x;

    // Fused cumsum: threads 0..127 = 64 pixels x 2 components.
    if (tid < 128) {
        int comp = tid >> 6;
        int pl   = tid & 63;
        const float* fb = flows + ((size_t)b * LL * 2 + comp) * HW + p_base + pl;
        float c = 0.0f;
#pragma unroll
        for (int l = 0; l < LL; l++) {
            c += fb[l * 2 * HW];
            ((float*)&scum[l * 64 + pl])[comp] = c;
        }
    }
    __syncthreads();

    int pl = tid >> 2;
    int q  = tid & 3;
    int xq = q >> 1;                  // left/right column
    int cq = q & 1;                   // channel octet
    int p  = p_base + pl;
    int h  = p >> 6;
    int w  = p & 63;
    float wc = (w + 0.5f);
    float hc = (h + 0.5f);

    // base ptr: image series + (+1,+1) pad origin + lane column/octet offset
    const char* ib0 = (const char*)g_pad
                    + (size_t)(b * LL) * IMG_BYTES
                    + (size_t)((PW + 1 + xq) * 32 + cq * 16);

#pragma unroll
    for (int pass = 0; pass < 2; pass++) {
        int t = pass ? r : (15 - r);

        float2 ct = scum[t * 64 + pl];
        float cwx = fmaf(32.0f, ct.x, wc);
        float cwy = fmaf(32.0f, ct.y, hc);

        __half2 zero = __float2half2_rn(0.0f);
        __half2 acc0 = zero, acc1 = zero, acc2 = zero, acc3 = zero;

        const char* kb = ib0;
#pragma unroll 1
        for (int k = 0; k <= t; k++, kb += IMG_BYTES) {
            float2 ck = scum[k * 64 + pl];
            float uxp = fmaf(-32.0f, ck.x, cwx);
            float uyp = fmaf(-32.0f, ck.y, cwy);
            // mod into [0,64): rxm == true rx + 0.5
            float rxm = fmaf(-floorf(uxp * 0.015625f), 64.0f, uxp);
            float rym = fmaf(-floorf(uyp * 0.015625f), 64.0f, uyp);
            float rx0 = rxm - 0.5f;
            float ry0 = rym - 0.5f;
            float fx0 = floorf(rx0);
            float fy0 = floorf(ry0);
            int x0 = (int)fx0;        // [-1, 63]
            int y0 = (int)fy0;
            float sx = rx0 - fx0;
            float sy = ry0 - fy0;
            float axw = 1.0f - sx;
            float ayw = 1.0f - sy;

            float xw = xq ? sx : axw;     // this lane's column weight
            __half2 wt2 = __float2half2_rn(xw * ayw);
            __half2 wb2 = __float2half2_rn(xw * sy);

            const char* addr = kb + (y0 * PW + x0) * 32;
            uint4 top = *(const uint4*)(addr);
            uint4 bot = *(const uint4*)(addr + PW * 32);

            const __half2* tp = (const __half2*)&top;
            const __half2* bp = (const __half2*)&bot;
            acc0 = __hfma2(tp[0], wt2, acc0);  acc0 = __hfma2(bp[0], wb2, acc0);
            acc1 = __hfma2(tp[1], wt2, acc1);  acc1 = __hfma2(bp[1], wb2, acc1);
            acc2 = __hfma2(tp[2], wt2, acc2);  acc2 = __hfma2(bp[2], wb2, acc2);
            acc3 = __hfma2(tp[3], wt2, acc3);  acc3 = __hfma2(bp[3], wb2, acc3);
        }

        // Merge left/right columns (partner lane q^2: same pixel, same octet)
        __half2 accv[4] = {acc0, acc1, acc2, acc3};
#pragma unroll
        for (int j = 0; j < 4; j++) {
            unsigned v = __shfl_xor_sync(0xffffffffu, *(unsigned*)&accv[j], 2);
            accv[j] = __hadd2(accv[j], *(__half2*)&v);
        }

        if (xq == 0) {
            // out layout (B,L,C,H,W); this lane owns channels [cq*8, cq*8+8)
            float* ob = out + ((size_t)(b * LL + t) * CC + cq * 8) * HW + p;
#pragma unroll
            for (int j = 0; j < 4; j++) {
                float2 f = __half22float2(accv[j]);
                ob[(2*j)     * HW] = f.x;
                ob[(2*j + 1) * HW] = f.y;
            }
        }
    }
}

// ---------------------------------------------------------------------------
extern "C" void kernel_launch(void* const* d_in, const int* in_sizes, int n_in,
                              void* d_out, int out_size) {
    const float* flows  = (const float*)d_in[0];
    const float* images = (const float*)d_in[1];
    if (n_in >= 2 && in_sizes[0] > in_sizes[1]) {   // defensive: flows is smaller
        const float* tmp = flows; flows = images; images = tmp;
    }
    float* out = (float*)d_out;

    pad_kernel<<<(BB * LL * PCH + 255) / 256, 256>>>(images);
    main_kernel<<<BB * 8 * 64, 256>>>(flows, out);
}